// round 1
// baseline (speedup 1.0000x reference)
#include <cuda_runtime.h>
#include <math.h>

// Problem-size constants (fixed by the dataset)
#define NN 80000
#define DD 64
#define EE 1280000

// Scratch: __device__ globals (no allocation allowed in kernel_launch).
// float4 typing guarantees 16B alignment for vector red.
__device__ float4 g_h4[NN * 16];    // h = X@W, later overwritten with H = relu(...)
__device__ float4 g_agg4[NN * 16];  // scatter accumulator
__device__ float  g_dinv[NN];
__device__ float  g_gg[NN];
__device__ int    g_cnt[NN];
__device__ int    g_deg[NN];

// ---------------------------------------------------------------------------
// k_init: zero agg, gg; deg starts at 1 (self loop); cnt=0.
// Runs inside the graph every replay, so state is reset each call.
// ---------------------------------------------------------------------------
__global__ void k_init(int n) {
    int i = blockIdx.x * blockDim.x + threadIdx.x;
    if (i < n * 16) g_agg4[i] = make_float4(0.f, 0.f, 0.f, 0.f);
    if (i < n) {
        g_deg[i] = 1;
        g_cnt[i] = 0;
        g_gg[i]  = 0.f;
    }
}

// ---------------------------------------------------------------------------
// k_deg: deg[dst]++ (in-degree + self loop), cnt[src]++ (G2 gate denominator)
// ---------------------------------------------------------------------------
__global__ void k_deg(const int* __restrict__ src, const int* __restrict__ dst, int e) {
    int i = blockIdx.x * blockDim.x + threadIdx.x;
    if (i < e) {
        atomicAdd(&g_deg[dst[i]], 1);
        atomicAdd(&g_cnt[src[i]], 1);
    }
}

__global__ void k_dinv(int n) {
    int i = blockIdx.x * blockDim.x + threadIdx.x;
    if (i < n) g_dinv[i] = rsqrtf((float)g_deg[i]);
}

// ---------------------------------------------------------------------------
// k_gemm: h = X @ W.  One thread per row; W staged in shared as float4.
// Inner k-loop fully unrolled (64 FFMA*4 + 64 LDS.128 per c-iteration).
// ---------------------------------------------------------------------------
__global__ void k_gemm(const float* __restrict__ X, const float* __restrict__ W, int n) {
    __shared__ float4 Wsh[64 * 16];
    for (int i = threadIdx.x; i < 64 * 16; i += blockDim.x)
        Wsh[i] = ((const float4*)W)[i];
    __syncthreads();

    int row = blockIdx.x * blockDim.x + threadIdx.x;
    if (row >= n) return;

    float x[64];
    const float4* xr = (const float4*)(X + (size_t)row * 64);
#pragma unroll
    for (int i = 0; i < 16; i++) {
        float4 v = xr[i];
        x[4 * i + 0] = v.x; x[4 * i + 1] = v.y;
        x[4 * i + 2] = v.z; x[4 * i + 3] = v.w;
    }

#pragma unroll 1
    for (int c = 0; c < 16; c++) {
        float4 acc = make_float4(0.f, 0.f, 0.f, 0.f);
#pragma unroll
        for (int k = 0; k < 64; k++) {
            float4 w = Wsh[k * 16 + c];
            acc.x += x[k] * w.x;
            acc.y += x[k] * w.y;
            acc.z += x[k] * w.z;
            acc.w += x[k] * w.w;
        }
        g_h4[row * 16 + c] = acc;
    }
}

// ---------------------------------------------------------------------------
// k_scatter: agg[dst] += h[src] * dinv[src]*dinv[dst]
// 16 lanes per edge, each lane owns a float4 chunk; red.global.add.v4.f32
// (PTX ISA 8.1, sm_90+) does 4 floats per atomic op.
// ---------------------------------------------------------------------------
__global__ void k_scatter(const int* __restrict__ src, const int* __restrict__ dst, int e) {
    int t = blockIdx.x * blockDim.x + threadIdx.x;
    int ei = t >> 4;
    int lane = t & 15;
    if (ei >= e) return;
    int s = src[ei];
    int d = dst[ei];
    float norm = g_dinv[s] * g_dinv[d];
    float4 hv = g_h4[s * 16 + lane];
    float4* addr = &g_agg4[d * 16 + lane];
    asm volatile(
        "red.global.add.v4.f32 [%0], {%1, %2, %3, %4};"
        :: "l"(addr),
           "f"(hv.x * norm), "f"(hv.y * norm), "f"(hv.z * norm), "f"(hv.w * norm)
        : "memory");
}

// ---------------------------------------------------------------------------
// k_relu: H = relu(agg + h*dinv^2 + b)   (self-loop term folded in here)
// Overwrites g_h4 with H.
// ---------------------------------------------------------------------------
__global__ void k_relu(const float* __restrict__ b, int n) {
    int i = blockIdx.x * blockDim.x + threadIdx.x;
    if (i >= n * 16) return;
    int v = i >> 4;
    int c = i & 15;
    float di = g_dinv[v];
    float sl = di * di;
    float4 a = g_agg4[i];
    float4 h = g_h4[i];
    float4 bb = ((const float4*)b)[c];
    float4 r;
    r.x = fmaxf(fmaf(h.x, sl, a.x) + bb.x, 0.f);
    r.y = fmaxf(fmaf(h.y, sl, a.y) + bb.y, 0.f);
    r.z = fmaxf(fmaf(h.z, sl, a.z) + bb.z, 0.f);
    r.w = fmaxf(fmaf(h.w, sl, a.w) + bb.w, 0.f);
    g_h4[i] = r;
}

// ---------------------------------------------------------------------------
// k_gate: gg[src] += sum_j (H[src,j]-H[dst,j])^2   (P = 2.0 exactly)
// 16 lanes per edge; xor-shuffle reduction within the 16-lane group.
// ---------------------------------------------------------------------------
__global__ void k_gate(const int* __restrict__ src, const int* __restrict__ dst, int e) {
    int t = blockIdx.x * blockDim.x + threadIdx.x;
    int ei = t >> 4;
    int lane = t & 15;
    if (ei >= e) return;
    int r = src[ei];
    int c = dst[ei];
    float4 a = g_h4[r * 16 + lane];
    float4 b = g_h4[c * 16 + lane];
    float dx = a.x - b.x, dy = a.y - b.y, dz = a.z - b.z, dw = a.w - b.w;
    float s = dx * dx + dy * dy + dz * dz + dw * dw;
    s += __shfl_xor_sync(0xffffffffu, s, 8);
    s += __shfl_xor_sync(0xffffffffu, s, 4);
    s += __shfl_xor_sync(0xffffffffu, s, 2);
    s += __shfl_xor_sync(0xffffffffu, s, 1);
    if (lane == 0) atomicAdd(&g_gg[r], s);
}

__global__ void k_out(float* __restrict__ out, int n) {
    int i = blockIdx.x * blockDim.x + threadIdx.x;
    if (i < n) out[i] = tanhf(g_gg[i] / fmaxf((float)g_cnt[i], 1.f));
}

// ---------------------------------------------------------------------------
extern "C" void kernel_launch(void* const* d_in, const int* in_sizes, int n_in,
                              void* d_out, int out_size) {
    const float* X  = (const float*)d_in[0];
    const int*   ei = (const int*)d_in[1];
    const float* W  = (const float*)d_in[2];
    const float* b  = (const float*)d_in[3];
    float* out = (float*)d_out;

    int n = in_sizes[0] / DD;   // 80000
    int e = in_sizes[1] / 2;    // 1280000
    const int* src = ei;
    const int* dst = ei + e;

    const int T = 256;
    int g_n16 = (n * 16 + T - 1) / T;
    int g_n   = (n + T - 1) / T;
    int g_e   = (e + T - 1) / T;
    long long e16 = (long long)e * 16;
    int g_e16 = (int)((e16 + T - 1) / T);

    k_init<<<g_n16, T>>>(n);
    k_deg<<<g_e, T>>>(src, dst, e);
    k_dinv<<<g_n, T>>>(n);
    k_gemm<<<g_n, T>>>(X, W, n);
    k_scatter<<<g_e16, T>>>(src, dst, e);
    k_relu<<<g_n16, T>>>(b, n);
    k_gate<<<g_e16, T>>>(src, dst, e);
    k_out<<<g_n, T>>>(out, n);
}

// round 2
// speedup vs baseline: 1.0017x; 1.0017x over previous
#include <cuda_runtime.h>
#include <math.h>

// Problem-size constants (fixed by the dataset)
#define NN 80000
#define DD 64
#define EE 1280000

// Scratch: __device__ globals (no allocation allowed in kernel_launch).
// float4 typing guarantees 16B alignment for vector red.
__device__ float4 g_h4[NN * 16];    // h = X@W, later overwritten with H = relu(...)
__device__ float4 g_agg4[NN * 16];  // scatter accumulator
__device__ float  g_dinv[NN];
__device__ float  g_gg[NN];
__device__ int    g_cnt[NN];
__device__ int    g_deg[NN];

// ---------------------------------------------------------------------------
// k_init: zero agg, gg; deg starts at 1 (self loop); cnt=0.
// Runs inside the graph every replay, so state is reset each call.
// ---------------------------------------------------------------------------
__global__ void k_init(int n) {
    int i = blockIdx.x * blockDim.x + threadIdx.x;
    if (i < n * 16) g_agg4[i] = make_float4(0.f, 0.f, 0.f, 0.f);
    if (i < n) {
        g_deg[i] = 1;
        g_cnt[i] = 0;
        g_gg[i]  = 0.f;
    }
}

// ---------------------------------------------------------------------------
// k_deg: deg[dst]++ (in-degree + self loop), cnt[src]++ (G2 gate denominator)
// ---------------------------------------------------------------------------
__global__ void k_deg(const int* __restrict__ src, const int* __restrict__ dst, int e) {
    int i = blockIdx.x * blockDim.x + threadIdx.x;
    if (i < e) {
        atomicAdd(&g_deg[dst[i]], 1);
        atomicAdd(&g_cnt[src[i]], 1);
    }
}

__global__ void k_dinv(int n) {
    int i = blockIdx.x * blockDim.x + threadIdx.x;
    if (i < n) g_dinv[i] = rsqrtf((float)g_deg[i]);
}

// ---------------------------------------------------------------------------
// k_gemm: h = X @ W.  One thread per row; W staged in shared as float4.
// Inner k-loop fully unrolled (64 FFMA*4 + 64 LDS.128 per c-iteration).
// ---------------------------------------------------------------------------
__global__ void k_gemm(const float* __restrict__ X, const float* __restrict__ W, int n) {
    __shared__ float4 Wsh[64 * 16];
    for (int i = threadIdx.x; i < 64 * 16; i += blockDim.x)
        Wsh[i] = ((const float4*)W)[i];
    __syncthreads();

    int row = blockIdx.x * blockDim.x + threadIdx.x;
    if (row >= n) return;

    float x[64];
    const float4* xr = (const float4*)(X + (size_t)row * 64);
#pragma unroll
    for (int i = 0; i < 16; i++) {
        float4 v = xr[i];
        x[4 * i + 0] = v.x; x[4 * i + 1] = v.y;
        x[4 * i + 2] = v.z; x[4 * i + 3] = v.w;
    }

#pragma unroll 1
    for (int c = 0; c < 16; c++) {
        float4 acc = make_float4(0.f, 0.f, 0.f, 0.f);
#pragma unroll
        for (int k = 0; k < 64; k++) {
            float4 w = Wsh[k * 16 + c];
            acc.x += x[k] * w.x;
            acc.y += x[k] * w.y;
            acc.z += x[k] * w.z;
            acc.w += x[k] * w.w;
        }
        g_h4[row * 16 + c] = acc;
    }
}

// ---------------------------------------------------------------------------
// k_scatter: agg[dst] += h[src] * dinv[src]*dinv[dst]
// 16 lanes per edge, each lane owns a float4 chunk; red.global.add.v4.f32
// (PTX ISA 8.1, sm_90+) does 4 floats per atomic op.
// ---------------------------------------------------------------------------
__global__ void k_scatter(const int* __restrict__ src, const int* __restrict__ dst, int e) {
    int t = blockIdx.x * blockDim.x + threadIdx.x;
    int ei = t >> 4;
    int lane = t & 15;
    if (ei >= e) return;
    int s = src[ei];
    int d = dst[ei];
    float norm = g_dinv[s] * g_dinv[d];
    float4 hv = g_h4[s * 16 + lane];
    float4* addr = &g_agg4[d * 16 + lane];
    asm volatile(
        "red.global.add.v4.f32 [%0], {%1, %2, %3, %4};"
        :: "l"(addr),
           "f"(hv.x * norm), "f"(hv.y * norm), "f"(hv.z * norm), "f"(hv.w * norm)
        : "memory");
}

// ---------------------------------------------------------------------------
// k_relu: H = relu(agg + h*dinv^2 + b)   (self-loop term folded in here)
// Overwrites g_h4 with H.
// ---------------------------------------------------------------------------
__global__ void k_relu(const float* __restrict__ b, int n) {
    int i = blockIdx.x * blockDim.x + threadIdx.x;
    if (i >= n * 16) return;
    int v = i >> 4;
    int c = i & 15;
    float di = g_dinv[v];
    float sl = di * di;
    float4 a = g_agg4[i];
    float4 h = g_h4[i];
    float4 bb = ((const float4*)b)[c];
    float4 r;
    r.x = fmaxf(fmaf(h.x, sl, a.x) + bb.x, 0.f);
    r.y = fmaxf(fmaf(h.y, sl, a.y) + bb.y, 0.f);
    r.z = fmaxf(fmaf(h.z, sl, a.z) + bb.z, 0.f);
    r.w = fmaxf(fmaf(h.w, sl, a.w) + bb.w, 0.f);
    g_h4[i] = r;
}

// ---------------------------------------------------------------------------
// k_gate: gg[src] += sum_j (H[src,j]-H[dst,j])^2   (P = 2.0 exactly)
// 16 lanes per edge; xor-shuffle reduction within the 16-lane group.
// ---------------------------------------------------------------------------
__global__ void k_gate(const int* __restrict__ src, const int* __restrict__ dst, int e) {
    int t = blockIdx.x * blockDim.x + threadIdx.x;
    int ei = t >> 4;
    int lane = t & 15;
    if (ei >= e) return;
    int r = src[ei];
    int c = dst[ei];
    float4 a = g_h4[r * 16 + lane];
    float4 b = g_h4[c * 16 + lane];
    float dx = a.x - b.x, dy = a.y - b.y, dz = a.z - b.z, dw = a.w - b.w;
    float s = dx * dx + dy * dy + dz * dz + dw * dw;
    s += __shfl_xor_sync(0xffffffffu, s, 8);
    s += __shfl_xor_sync(0xffffffffu, s, 4);
    s += __shfl_xor_sync(0xffffffffu, s, 2);
    s += __shfl_xor_sync(0xffffffffu, s, 1);
    if (lane == 0) atomicAdd(&g_gg[r], s);
}

__global__ void k_out(float* __restrict__ out, int n) {
    int i = blockIdx.x * blockDim.x + threadIdx.x;
    if (i < n) out[i] = tanhf(g_gg[i] / fmaxf((float)g_cnt[i], 1.f));
}

// ---------------------------------------------------------------------------
extern "C" void kernel_launch(void* const* d_in, const int* in_sizes, int n_in,
                              void* d_out, int out_size) {
    const float* X  = (const float*)d_in[0];
    const int*   ei = (const int*)d_in[1];
    const float* W  = (const float*)d_in[2];
    const float* b  = (const float*)d_in[3];
    float* out = (float*)d_out;

    int n = in_sizes[0] / DD;   // 80000
    int e = in_sizes[1] / 2;    // 1280000
    const int* src = ei;
    const int* dst = ei + e;

    const int T = 256;
    int g_n16 = (n * 16 + T - 1) / T;
    int g_n   = (n + T - 1) / T;
    int g_e   = (e + T - 1) / T;
    long long e16 = (long long)e * 16;
    int g_e16 = (int)((e16 + T - 1) / T);

    k_init<<<g_n16, T>>>(n);
    k_deg<<<g_e, T>>>(src, dst, e);
    k_dinv<<<g_n, T>>>(n);
    k_gemm<<<g_n, T>>>(X, W, n);
    k_scatter<<<g_e16, T>>>(src, dst, e);
    k_relu<<<g_n16, T>>>(b, n);
    k_gate<<<g_e16, T>>>(src, dst, e);
    k_out<<<g_n, T>>>(out, n);
}

// round 3
// speedup vs baseline: 1.2353x; 1.2332x over previous
#include <cuda_runtime.h>
#include <cuda_fp16.h>
#include <math.h>

#define NN 80000
#define DD 64
#define EE 1280000

// Scratch (__device__ globals; no allocation allowed in kernel_launch)
__device__ float4 g_h4[NN * 16];    // h = X@W (fp32)
__device__ float4 g_agg4[NN * 16];  // scatter accumulator
__device__ uint2  g_H2[NN * 16];    // H = relu(...) packed as 4x half per uint2
__device__ float  g_dinv[NN];
__device__ float  g_gg[NN];
__device__ int    g_cnt[NN];
__device__ int    g_deg[NN];

// ---------------------------------------------------------------------------
__global__ void k_init(int n) {
    int i = blockIdx.x * blockDim.x + threadIdx.x;
    if (i < n * 16) g_agg4[i] = make_float4(0.f, 0.f, 0.f, 0.f);
    if (i < n) {
        g_deg[i] = 1;   // self loop
        g_cnt[i] = 0;
        g_gg[i]  = 0.f;
    }
}

__global__ void k_deg(const int* __restrict__ src, const int* __restrict__ dst, int e) {
    int i = blockIdx.x * blockDim.x + threadIdx.x;
    if (i < e) {
        atomicAdd(&g_deg[dst[i]], 1);
        atomicAdd(&g_cnt[src[i]], 1);
    }
}

__global__ void k_dinv(int n) {
    int i = blockIdx.x * blockDim.x + threadIdx.x;
    if (i < n) g_dinv[i] = rsqrtf((float)g_deg[i]);
}

// ---------------------------------------------------------------------------
// k_gemm: h = X @ W, register-tiled.
// Block = 256 threads covers 64 rows x 64 cols. Thread (rg,cg) computes a
// 4-row x 4-col output tile: per k-step, 2 LDS.128 feed 16 FFMA.
// X is staged transposed (k-major) in smem so 4 consecutive rows form a float4.
// ---------------------------------------------------------------------------
#define XS_STRIDE 68   // 64 rows + 4 pad; (68*4) % 16 == 0 keeps float4 alignment
__global__ void __launch_bounds__(256) k_gemm(const float* __restrict__ X,
                                              const float* __restrict__ W, int n) {
    __shared__ float  Xsh[64 * XS_STRIDE];   // Xsh[k][row]
    __shared__ float4 Wsh[64 * 16];          // Wsh[k][cg]  (row-major copy of W)

    int tid  = threadIdx.x;
    int base = blockIdx.x * 64;

    // Stage W: 1024 float4, 4 per thread (straight copy).
    const float4* W4 = (const float4*)W;
#pragma unroll
    for (int i = 0; i < 4; i++) Wsh[tid + 256 * i] = W4[tid + 256 * i];

    // Stage X transposed: each thread loads 4 float4 (row, k-chunk), scatters
    // 4 scalars each into Xsh[k][row].
#pragma unroll
    for (int i = 0; i < 4; i++) {
        int idx = tid + 256 * i;         // 0..1023
        int row = idx & 63;
        int kk  = idx >> 6;              // float4 index along k: 0..15
        int gr  = base + row;
        float4 v = (gr < n) ? ((const float4*)(X + (size_t)gr * 64))[kk]
                            : make_float4(0.f, 0.f, 0.f, 0.f);
        int k0 = kk * 4;
        Xsh[(k0 + 0) * XS_STRIDE + row] = v.x;
        Xsh[(k0 + 1) * XS_STRIDE + row] = v.y;
        Xsh[(k0 + 2) * XS_STRIDE + row] = v.z;
        Xsh[(k0 + 3) * XS_STRIDE + row] = v.w;
    }
    __syncthreads();

    int cg = tid & 15;        // col group (4 cols)
    int rg = tid >> 4;        // row group (4 rows)

    float4 acc0 = make_float4(0.f, 0.f, 0.f, 0.f);
    float4 acc1 = make_float4(0.f, 0.f, 0.f, 0.f);
    float4 acc2 = make_float4(0.f, 0.f, 0.f, 0.f);
    float4 acc3 = make_float4(0.f, 0.f, 0.f, 0.f);

#pragma unroll
    for (int k = 0; k < 64; k++) {
        float4 w  = Wsh[k * 16 + cg];
        float4 xv = *(const float4*)&Xsh[k * XS_STRIDE + rg * 4];
        acc0.x += xv.x * w.x; acc0.y += xv.x * w.y; acc0.z += xv.x * w.z; acc0.w += xv.x * w.w;
        acc1.x += xv.y * w.x; acc1.y += xv.y * w.y; acc1.z += xv.y * w.z; acc1.w += xv.y * w.w;
        acc2.x += xv.z * w.x; acc2.y += xv.z * w.y; acc2.z += xv.z * w.z; acc2.w += xv.z * w.w;
        acc3.x += xv.w * w.x; acc3.y += xv.w * w.y; acc3.z += xv.w * w.z; acc3.w += xv.w * w.w;
    }

    int r0 = base + rg * 4;
    if (r0 + 0 < n) g_h4[(r0 + 0) * 16 + cg] = acc0;
    if (r0 + 1 < n) g_h4[(r0 + 1) * 16 + cg] = acc1;
    if (r0 + 2 < n) g_h4[(r0 + 2) * 16 + cg] = acc2;
    if (r0 + 3 < n) g_h4[(r0 + 3) * 16 + cg] = acc3;
}

// ---------------------------------------------------------------------------
// k_scatter: agg[dst] += h[src] * dinv[src]*dinv[dst]
// 16 lanes/edge; red.global.add.v4.f32 = 4 floats per atomic op.
// ---------------------------------------------------------------------------
__global__ void k_scatter(const int* __restrict__ src, const int* __restrict__ dst, int e) {
    int t = blockIdx.x * blockDim.x + threadIdx.x;
    int ei = t >> 4;
    int lane = t & 15;
    if (ei >= e) return;
    int s = src[ei];
    int d = dst[ei];
    float norm = g_dinv[s] * g_dinv[d];
    float4 hv = g_h4[s * 16 + lane];
    float4* addr = &g_agg4[d * 16 + lane];
    asm volatile(
        "red.global.add.v4.f32 [%0], {%1, %2, %3, %4};"
        :: "l"(addr),
           "f"(hv.x * norm), "f"(hv.y * norm), "f"(hv.z * norm), "f"(hv.w * norm)
        : "memory");
}

// ---------------------------------------------------------------------------
// k_relu: H = relu(agg + h*dinv^2 + b), written as packed fp16 (half2 pairs).
// ---------------------------------------------------------------------------
__global__ void k_relu(const float* __restrict__ b, int n) {
    int i = blockIdx.x * blockDim.x + threadIdx.x;
    if (i >= n * 16) return;
    int v = i >> 4;
    int c = i & 15;
    float di = g_dinv[v];
    float sl = di * di;
    float4 a = g_agg4[i];
    float4 h = g_h4[i];
    float4 bb = ((const float4*)b)[c];
    float rx = fmaxf(fmaf(h.x, sl, a.x) + bb.x, 0.f);
    float ry = fmaxf(fmaf(h.y, sl, a.y) + bb.y, 0.f);
    float rz = fmaxf(fmaf(h.z, sl, a.z) + bb.z, 0.f);
    float rw = fmaxf(fmaf(h.w, sl, a.w) + bb.w, 0.f);
    __half2 lo = __floats2half2_rn(rx, ry);
    __half2 hi = __floats2half2_rn(rz, rw);
    uint2 packed;
    packed.x = *(unsigned int*)&lo;
    packed.y = *(unsigned int*)&hi;
    g_H2[i] = packed;
}

// ---------------------------------------------------------------------------
// k_gate: gg[src] += sum_j (H[src,j]-H[dst,j])^2 on fp16 H (fp32 math).
// 8 lanes/edge, each lane owns 8 halves (one uint4 = 16B); 128B per vector.
// ---------------------------------------------------------------------------
__global__ void k_gate(const int* __restrict__ src, const int* __restrict__ dst, int e) {
    int t = blockIdx.x * blockDim.x + threadIdx.x;
    int ei = t >> 3;
    int lane = t & 7;
    if (ei >= e) return;
    int r = src[ei];
    int c = dst[ei];
    const uint4* H = (const uint4*)g_H2;   // 8 uint4 per node row
    uint4 a = __ldg(&H[r * 8 + lane]);
    uint4 b = __ldg(&H[c * 8 + lane]);
    const unsigned int* au = (const unsigned int*)&a;
    const unsigned int* bu = (const unsigned int*)&b;
    float s = 0.f;
#pragma unroll
    for (int j = 0; j < 4; j++) {
        float2 fa = __half22float2(*(const __half2*)&au[j]);
        float2 fb = __half22float2(*(const __half2*)&bu[j]);
        float d0 = fa.x - fb.x;
        float d1 = fa.y - fb.y;
        s = fmaf(d0, d0, s);
        s = fmaf(d1, d1, s);
    }
    s += __shfl_xor_sync(0xffffffffu, s, 4);
    s += __shfl_xor_sync(0xffffffffu, s, 2);
    s += __shfl_xor_sync(0xffffffffu, s, 1);
    if (lane == 0) atomicAdd(&g_gg[r], s);
}

__global__ void k_out(float* __restrict__ out, int n) {
    int i = blockIdx.x * blockDim.x + threadIdx.x;
    if (i < n) out[i] = tanhf(g_gg[i] / fmaxf((float)g_cnt[i], 1.f));
}

// ---------------------------------------------------------------------------
extern "C" void kernel_launch(void* const* d_in, const int* in_sizes, int n_in,
                              void* d_out, int out_size) {
    const float* X  = (const float*)d_in[0];
    const int*   ei = (const int*)d_in[1];
    const float* W  = (const float*)d_in[2];
    const float* b  = (const float*)d_in[3];
    float* out = (float*)d_out;

    int n = in_sizes[0] / DD;   // 80000
    int e = in_sizes[1] / 2;    // 1280000
    const int* src = ei;
    const int* dst = ei + e;

    const int T = 256;
    int g_n16 = (n * 16 + T - 1) / T;
    int g_n   = (n + T - 1) / T;
    int g_e   = (e + T - 1) / T;
    int g_rows = (n + 63) / 64;
    long long e16 = (long long)e * 16;
    int g_e16 = (int)((e16 + T - 1) / T);
    long long e8 = (long long)e * 8;
    int g_e8 = (int)((e8 + T - 1) / T);

    k_init<<<g_n16, T>>>(n);
    k_deg<<<g_e, T>>>(src, dst, e);
    k_dinv<<<g_n, T>>>(n);
    k_gemm<<<g_rows, T>>>(X, W, n);
    k_scatter<<<g_e16, T>>>(src, dst, e);
    k_relu<<<g_n16, T>>>(b, n);
    k_gate<<<g_e8, T>>>(src, dst, e);
    k_out<<<g_n, T>>>(out, n);
}